// round 14
// baseline (speedup 1.0000x reference)
#include <cuda_runtime.h>
#include <cuda_fp16.h>
#include <math.h>

typedef long long ll;
typedef unsigned u32;

#define Bn 8
#define NMELS 128
#define TIN 4096
#define T1 2048
#define S 1024
#define D 1024
#define H 8
#define DH 128
#define Fdim 4096
#define NTOK (Bn*S)
#define Ldim 6

// ---------------- fp32 scratch ----------------
__device__ float g_x [(size_t)NTOK*D];             // residual stream

// ---------------- fp16 buffers ----------------
__device__ __align__(256) half g_h1[(size_t)Bn*T1*D];   // conv1 out [b][t][d]
__device__ __align__(256) half c1w[(size_t)D*384];
__device__ __align__(256) half c2w[(size_t)D*3072];     // reordered: [d][kk*1024+i]
__device__ __align__(256) half wq[(size_t)Ldim*D*D];
__device__ __align__(256) half wk[(size_t)Ldim*D*D];
__device__ __align__(256) half wv[(size_t)Ldim*D*D];
__device__ __align__(256) half wo[(size_t)Ldim*D*D];
__device__ __align__(256) half w1[(size_t)Ldim*Fdim*D];
__device__ __align__(256) half w2[(size_t)Ldim*Fdim*D];
__device__ __align__(256) half g_col[(size_t)Bn*T1*384];
__device__ __align__(256) half g_y [(size_t)NTOK*D];
__device__ __align__(256) half g_q [(size_t)NTOK*D];
__device__ __align__(256) half g_k [(size_t)NTOK*D];
__device__ __align__(256) half g_vt[(size_t)D*NTOK];
__device__ __align__(256) half g_m1[(size_t)NTOK*Fdim];
__device__ __align__(256) half g_o [(size_t)NTOK*D];

// ---------------- helpers ----------------
__device__ __forceinline__ float gelu_exact(float v) {
    return 0.5f * v * (1.0f + erff(v * 0.70710678118654752f));
}
__device__ __forceinline__ void mma_fp16(float* d, const u32* a, const u32* b) {
    asm volatile(
        "mma.sync.aligned.m16n8k16.row.col.f32.f16.f16.f32 "
        "{%0,%1,%2,%3}, {%4,%5,%6,%7}, {%8,%9}, {%0,%1,%2,%3};\n"
        : "+f"(d[0]), "+f"(d[1]), "+f"(d[2]), "+f"(d[3])
        : "r"(a[0]), "r"(a[1]), "r"(a[2]), "r"(a[3]), "r"(b[0]), "r"(b[1]));
}
__device__ __forceinline__ void ldsm4(u32* r, u32 addr) {
    asm volatile("ldmatrix.sync.aligned.m8n8.x4.shared.b16 {%0,%1,%2,%3}, [%4];\n"
        : "=r"(r[0]), "=r"(r[1]), "=r"(r[2]), "=r"(r[3]) : "r"(addr));
}
__device__ __forceinline__ void cpa16(u32 dst, const void* src) {
    asm volatile("cp.async.cg.shared.global [%0], [%1], 16;\n" :: "r"(dst), "l"(src));
}
__device__ __forceinline__ void cpa16p(u32 dst, const void* src, int pred) {
    int sz = pred ? 16 : 0;
    asm volatile("cp.async.cg.shared.global [%0], [%1], 16, %2;\n" :: "r"(dst), "l"(src), "r"(sz));
}
__device__ __forceinline__ u32 packh2(float lo, float hi) {
    __half2 h = __floats2half2_rn(lo, hi);
    return *(u32*)&h;
}

// ---------------- fp16 tensor-core GEMM (16 warps, 128x256 tile, KC=64, 3-stage) ----------------
// C[M,N] = A[M,K] * B[N,K]^T
#define KC 64
#define NSTG 3
#define PADR 72
#define A_TILE_B (128*PADR*2)        // 18432
#define B_TILE_B (256*PADR*2)        // 36864
#define STG_B  (A_TILE_B+B_TILE_B)   // 55296
#define SMEM_TOT (NSTG*STG_B)        // 165888

struct GemmP {
    const half *A, *B;
    const half *Bk, *Bv;     // qkvZ weight pointers for z=1,2
    float* C; half *Cs;
    half *Qd, *Kd, *Vd;      // qkvZ outputs
    const float* Cin;
    const float* bias;
    const float* bias2;      // qkvZ: v bias
    int K, lda, ldb, ldc;
    int zDiv;
    ll sAo, sAi, sBo, sBi, sCo, sCi;
    int biasMode;   // 0 none, 1 per-col(n), 2 per-row(m)
    int addC;
    int act;        // 0 none, 1 exact GELU, 2 RoPE+scale
    int transStore;
    int outF32, outHalf;
    int aConv;
    int qkvZ;       // grid.z selects q/k/v
};

__device__ __forceinline__ void rope2(float& v0, float& v1, int m, int cB) {
    int s = m & (S - 1);
    int j = (cB & 127) >> 1;
    float freq = powf(10000.f, -(float)(2 * j) * (1.f / 128.f));
    float ang = (float)s * freq;
    float cc, ss; sincosf(ang, &ss, &cc);
    const float sc = 0.29730177875068026f;  // 128^-0.25
    float r0 = (v0 * cc - v1 * ss) * sc;
    float r1 = (v0 * ss + v1 * cc) * sc;
    v0 = r0; v1 = r1;
}

__global__ __launch_bounds__(512, 1) void gemm_tc(GemmP p) {
    extern __shared__ __align__(16) half sm[];
    int z = blockIdx.z;
    ll offA = 0, offB = 0, offC = 0;
    const half* A = p.A;
    const half* B = p.B;
    if (p.qkvZ) {
        B = (z == 0) ? p.B : (z == 1) ? p.Bk : p.Bv;
    } else {
        offA = (ll)(z / p.zDiv) * p.sAo + (ll)(z % p.zDiv) * p.sAi;
        offB = (ll)(z / p.zDiv) * p.sBo + (ll)(z % p.zDiv) * p.sBi;
        offC = (ll)(z / p.zDiv) * p.sCo + (ll)(z % p.zDiv) * p.sCi;
        A += offA; B += offB;
    }

    int m0 = blockIdx.y * 128, n0 = blockIdx.x * 256;
    int tid = threadIdx.x, lane = tid & 31, wid = tid >> 5;
    int wm = (wid & 3) * 32, wn = (wid >> 2) * 64;
    u32 smu = (u32)__cvta_generic_to_shared(sm);

    float acc[2][8][4];
    #pragma unroll
    for (int a = 0; a < 2; a++)
        #pragma unroll
        for (int b = 0; b < 8; b++)
            #pragma unroll
            for (int c = 0; c < 4; c++) acc[a][b][c] = 0.f;

    int ldRow = tid >> 3;           // 0..63
    int ldCC  = (tid & 7) * 8;      // col within 64

    auto issue = [&](int c) {
        u32 base = smu + (u32)(c % NSTG) * STG_B;
        int k0 = c * KC;
        #pragma unroll
        for (int hh = 0; hh < 2; hh++) {
            int row = ldRow + hh * 64;
            u32 so = (u32)(row * PADR + ldCC) * 2;
            if (p.aConv) {
                int kk = k0 >> 10;
                int i0 = (k0 & 1023) + ldCC;
                int pos = 2 * (m0 + row) + kk - 1;
                const half* src = A + (ll)(pos < 0 ? 0 : pos) * 1024 + i0;
                cpa16p(base + so, src, pos >= 0);
            } else {
                cpa16(base + so, A + (ll)(m0 + row) * p.lda + k0 + ldCC);
            }
        }
        #pragma unroll
        for (int hh = 0; hh < 4; hh++) {
            int row = ldRow + hh * 64;
            u32 so = (u32)(row * PADR + ldCC) * 2;
            cpa16(base + A_TILE_B + so, B + (ll)(n0 + row) * p.ldb + k0 + ldCC);
        }
        asm volatile("cp.async.commit_group;" ::: "memory");
    };

    int nch = p.K / KC;
    issue(0);
    if (nch > 1) issue(1);

    for (int c = 0; c < nch; c++) {
        if (c + 1 < nch) asm volatile("cp.async.wait_group 1;" ::: "memory");
        else             asm volatile("cp.async.wait_group 0;" ::: "memory");
        __syncthreads();
        if (c + 2 < nch) issue(c + 2);

        u32 aB = smu + (u32)(c % NSTG) * STG_B;
        u32 bB = aB + A_TILE_B;

        #pragma unroll
        for (int ks = 0; ks < 4; ks++) {
            u32 ar[2][4], br[8][2];
            #pragma unroll
            for (int mi = 0; mi < 2; mi++) {
                int row = wm + mi * 16 + (lane & 15);
                int col = ks * 16 + (lane >> 4) * 8;
                ldsm4(ar[mi], aB + (u32)(row * PADR + col) * 2);
            }
            #pragma unroll
            for (int nj = 0; nj < 4; nj++) {
                int g = lane >> 3;
                int row = wn + nj * 16 + ((g >> 1) << 3) + (lane & 7);
                int col = ks * 16 + ((g & 1) << 3);
                u32 t[4];
                ldsm4(t, bB + (u32)(row * PADR + col) * 2);
                br[nj*2][0] = t[0]; br[nj*2][1] = t[1];
                br[nj*2+1][0] = t[2]; br[nj*2+1][1] = t[3];
            }
            #pragma unroll
            for (int mi = 0; mi < 2; mi++)
                #pragma unroll
                for (int nf = 0; nf < 8; nf++)
                    mma_fp16(acc[mi][nf], ar[mi], br[nf]);
        }
    }

    float* Cp = p.C  ? p.C  + offC : nullptr;
    half* Csp = p.Cs ? p.Cs + offC : nullptr;
    const float* Rp = p.Cin ? p.Cin + offC : Cp;
    #pragma unroll
    for (int mi = 0; mi < 2; mi++)
        #pragma unroll
        for (int nf = 0; nf < 8; nf++) {
            int rB = m0 + wm + mi * 16 + (lane >> 2);
            int cB = n0 + wn + nf * 8 + (lane & 3) * 2;
            #pragma unroll
            for (int pe = 0; pe < 2; pe++) {
                int m = rB + pe * 8;
                float v0 = acc[mi][nf][pe * 2 + 0];
                float v1 = acc[mi][nf][pe * 2 + 1];

                if (p.qkvZ) {
                    if (z == 0) {
                        v0 += p.bias[cB]; v1 += p.bias[cB + 1];
                        rope2(v0, v1, m, cB);
                        *(u32*)&p.Qd[(ll)m * D + cB] = packh2(v0, v1);
                    } else if (z == 1) {
                        rope2(v0, v1, m, cB);
                        *(u32*)&p.Kd[(ll)m * D + cB] = packh2(v0, v1);
                    } else {
                        v0 += p.bias2[cB]; v1 += p.bias2[cB + 1];
                        p.Vd[(ll)cB * NTOK + m]       = __float2half_rn(v0);
                        p.Vd[(ll)(cB + 1) * NTOK + m] = __float2half_rn(v1);
                    }
                    continue;
                }

                if (p.biasMode == 1) { v0 += p.bias[cB]; v1 += p.bias[cB + 1]; }
                else if (p.biasMode == 2) { float bb = p.bias[m]; v0 += bb; v1 += bb; }
                if (p.act == 1) { v0 = gelu_exact(v0); v1 = gelu_exact(v1); }
                else if (p.act == 2) rope2(v0, v1, m, cB);

                if (!p.transStore) {
                    ll off0 = (ll)m * p.ldc + cB;
                    if (p.outF32) {
                        float w0 = v0, w1 = v1;
                        if (p.addC) {
                            float2 o = *(const float2*)&Rp[off0];
                            w0 += o.x; w1 += o.y;
                        }
                        *(float2*)&Cp[off0] = make_float2(w0, w1);
                    }
                    if (p.outHalf) *(u32*)&Csp[off0] = packh2(v0, v1);
                } else {
                    ll off0 = (ll)cB * p.ldc + m;
                    ll off1 = off0 + p.ldc;
                    if (p.outF32) {
                        float w0 = v0, w1 = v1;
                        if (p.addC) { w0 += Rp[off0]; w1 += Rp[off1]; }
                        Cp[off0] = w0; Cp[off1] = w1;
                    }
                    if (p.outHalf) {
                        Csp[off0] = __float2half_rn(v0);
                        Csp[off1] = __float2half_rn(v1);
                    }
                }
            }
        }
}

// ---------------- fused flash attention ----------------
#define FP2 136
#define FSM_BYTES ((128+128+128)*FP2*2)    // 104448

__global__ __launch_bounds__(256) void attn_k(const int* __restrict__ x_len) {
    extern __shared__ __align__(16) half fsm[];
    int tid = threadIdx.x, lane = tid & 31, wid = tid >> 5;
    int bh = blockIdx.y, b = bh >> 3, h = bh & 7;
    int m0 = blockIdx.x * 128;
    int wm = wid * 16;
    u32 smu = (u32)__cvta_generic_to_shared(fsm);
    u32 sQ = smu;
    u32 sK = smu + (u32)(128 * FP2) * 2;
    u32 sV = sK + (u32)(128 * FP2) * 2;

    const half* qp = g_q + ((ll)(b * S + m0)) * D + h * 128;
    const half* kp = g_k + ((ll)b * S) * D + h * 128;
    const half* vp = g_vt + ((ll)(h * 128)) * NTOK + (ll)b * S;

    #pragma unroll
    for (int i = 0; i < 8; i++) {
        int idx = tid + 256 * i, row = idx >> 4, ch = idx & 15;
        cpa16(sQ + (u32)(row * FP2 + ch * 8) * 2, qp + (ll)row * D + ch * 8);
    }
    asm volatile("cp.async.commit_group;" ::: "memory");

    int xl = x_len[b];
    int quad = lane >> 2, qi = lane & 3;
    float mrow[2] = {-1e30f, -1e30f}, lrow[2] = {0.f, 0.f};
    float oacc[16][4];
    #pragma unroll
    for (int nt = 0; nt < 16; nt++)
        #pragma unroll
        for (int e = 0; e < 4; e++) oacc[nt][e] = 0.f;

    for (int kv0 = 0; kv0 < S; kv0 += 128) {
        if (kv0) __syncthreads();
        #pragma unroll
        for (int i = 0; i < 8; i++) {
            int idx = tid + 256 * i, row = idx >> 4, ch = idx & 15;
            cpa16(sK + (u32)(row * FP2 + ch * 8) * 2, kp + (ll)(kv0 + row) * D + ch * 8);
        }
        asm volatile("cp.async.commit_group;" ::: "memory");
        #pragma unroll
        for (int i = 0; i < 8; i++) {
            int idx = tid + 256 * i, row = idx >> 4, ch = idx & 15;
            cpa16(sV + (u32)(row * FP2 + ch * 8) * 2, vp + (ll)row * NTOK + kv0 + ch * 8);
        }
        asm volatile("cp.async.commit_group;" ::: "memory");
        asm volatile("cp.async.wait_group 1;" ::: "memory");
        __syncthreads();

        float sacc[16][4];
        #pragma unroll
        for (int nt = 0; nt < 16; nt++)
            #pragma unroll
            for (int e = 0; e < 4; e++) sacc[nt][e] = 0.f;

        #pragma unroll
        for (int ks = 0; ks < 8; ks++) {
            u32 aq[4];
            ldsm4(aq, sQ + (u32)((wm + (lane & 15)) * FP2 + ks * 16 + (lane >> 4) * 8) * 2);
            #pragma unroll
            for (int njp = 0; njp < 8; njp++) {
                int g = lane >> 3;
                int row = njp * 16 + ((g >> 1) << 3) + (lane & 7);
                int col = ks * 16 + ((g & 1) << 3);
                u32 t[4];
                ldsm4(t, sK + (u32)(row * FP2 + col) * 2);
                u32 b0[2] = {t[0], t[1]}, b1[2] = {t[2], t[3]};
                mma_fp16(sacc[njp*2],   aq, b0);
                mma_fp16(sacc[njp*2+1], aq, b1);
            }
        }

        float rmax[2] = {-1e30f, -1e30f};
        #pragma unroll
        for (int nt = 0; nt < 16; nt++)
            #pragma unroll
            for (int e = 0; e < 4; e++) {
                int col = kv0 + nt * 8 + qi * 2 + (e & 1);
                float v = sacc[nt][e] + ((4 * col + 3 < xl) ? 0.f : -1e10f);
                sacc[nt][e] = v;
                rmax[e >> 1] = fmaxf(rmax[e >> 1], v);
            }
        #pragma unroll
        for (int s2 = 1; s2 < 4; s2 <<= 1) {
            rmax[0] = fmaxf(rmax[0], __shfl_xor_sync(0xffffffff, rmax[0], s2));
            rmax[1] = fmaxf(rmax[1], __shfl_xor_sync(0xffffffff, rmax[1], s2));
        }
        float mn0 = fmaxf(mrow[0], rmax[0]), mn1 = fmaxf(mrow[1], rmax[1]);
        float sc0 = expf(mrow[0] - mn0), sc1 = expf(mrow[1] - mn1);
        float rsum[2] = {0.f, 0.f};
        #pragma unroll
        for (int nt = 0; nt < 16; nt++)
            #pragma unroll
            for (int e = 0; e < 4; e++) {
                float v = expf(sacc[nt][e] - ((e >> 1) ? mn1 : mn0));
                sacc[nt][e] = v;
                rsum[e >> 1] += v;
            }
        #pragma unroll
        for (int s2 = 1; s2 < 4; s2 <<= 1) {
            rsum[0] += __shfl_xor_sync(0xffffffff, rsum[0], s2);
            rsum[1] += __shfl_xor_sync(0xffffffff, rsum[1], s2);
        }
        lrow[0] = lrow[0] * sc0 + rsum[0];
        lrow[1] = lrow[1] * sc1 + rsum[1];
        mrow[0] = mn0; mrow[1] = mn1;
        #pragma unroll
        for (int nt = 0; nt < 16; nt++) {
            oacc[nt][0] *= sc0; oacc[nt][1] *= sc0;
            oacc[nt][2] *= sc1; oacc[nt][3] *= sc1;
        }

        asm volatile("cp.async.wait_group 0;" ::: "memory");
        __syncthreads();

        #pragma unroll
        for (int j = 0; j < 8; j++) {
            u32 af[4];
            af[0] = packh2(sacc[2*j][0],   sacc[2*j][1]);
            af[1] = packh2(sacc[2*j][2],   sacc[2*j][3]);
            af[2] = packh2(sacc[2*j+1][0], sacc[2*j+1][1]);
            af[3] = packh2(sacc[2*j+1][2], sacc[2*j+1][3]);
            #pragma unroll
            for (int njp = 0; njp < 8; njp++) {
                int g = lane >> 3;
                int row = njp * 16 + ((g >> 1) << 3) + (lane & 7);
                int col = j * 16 + ((g & 1) << 3);
                u32 t[4];
                ldsm4(t, sV + (u32)(row * FP2 + col) * 2);
                u32 b0[2] = {t[0], t[1]}, b1[2] = {t[2], t[3]};
                mma_fp16(oacc[njp*2],   af, b0);
                mma_fp16(oacc[njp*2+1], af, b1);
            }
        }
    }

    float inv0 = 1.f / lrow[0], inv1 = 1.f / lrow[1];
    half* op = g_o + ((ll)(b * S + m0 + wm)) * D + h * 128;
    #pragma unroll
    for (int nt = 0; nt < 16; nt++)
        #pragma unroll
        for (int pe = 0; pe < 2; pe++) {
            int row = quad + pe * 8;
            float iv = pe ? inv1 : inv0;
            u32 pk = packh2(oacc[nt][pe*2] * iv, oacc[nt][pe*2+1] * iv);
            *(u32*)&op[(ll)row * D + nt * 8 + qi * 2] = pk;
        }
}

// ---------------- weight converts (8 elems/thread, packed 16B store) ----------------
__global__ void cvt_k(const float* __restrict__ in, half* __restrict__ out, ll n) {
    ll i = ((ll)blockIdx.x * 256 + threadIdx.x) * 8;
    if (i >= n) return;
    float4 a = *(const float4*)&in[i];
    float4 b = *(const float4*)&in[i + 4];
    uint4 o;
    o.x = packh2(a.x, a.y);
    o.y = packh2(a.z, a.w);
    o.z = packh2(b.x, b.y);
    o.w = packh2(b.z, b.w);
    *(uint4*)&out[i] = o;
}
// conv2 weights: out[d][kk*1024+i] = in[d][i*3+kk]
__global__ void cvt_c2_k(const float* __restrict__ in, half* __restrict__ out) {
    ll idx = (ll)blockIdx.x * 256 + threadIdx.x;
    if (idx >= (ll)D * 3072) return;
    int rp = (int)(idx % 3072);
    int d  = (int)(idx / 3072);
    int kk = rp >> 10, i = rp & 1023;
    out[idx] = __float2half_rn(in[(ll)d * 3072 + i * 3 + kk]);
}

// ---------------- im2col for conv1 ----------------
__global__ void im2col1_k(const float* __restrict__ x) {
    int idx = blockIdx.x * 256 + threadIdx.x;
    const int total = Bn * T1 * 384;
    if (idx >= total) return;
    int r = idx % 384;
    int t = (idx / 384) % T1;
    int b = idx / (384 * T1);
    int i = r / 3, kk = r % 3;
    int pos = 2 * t + kk - 1;
    float v = (pos >= 0 && pos < TIN) ? x[((ll)b * NMELS + i) * TIN + pos] : 0.f;
    g_col[idx] = __float2half_rn(v);
}

// ---------------- LayerNorm -> fp16 ----------------
__global__ void ln_k(const float* __restrict__ x,
                     const float* __restrict__ w, const float* __restrict__ b) {
    int row = blockIdx.x;
    int tid = threadIdx.x;
    const float* xr = x + (ll)row * D;
    __shared__ float red[256];
    float v[4];
    #pragma unroll
    for (int i = 0; i < 4; i++) v[i] = xr[tid + 256 * i];
    float s = v[0] + v[1] + v[2] + v[3];
    red[tid] = s; __syncthreads();
    for (int o = 128; o > 0; o >>= 1) { if (tid < o) red[tid] += red[tid + o]; __syncthreads(); }
    float mean = red[0] * (1.f / D);
    __syncthreads();
    float sq = 0.f;
    #pragma unroll
    for (int i = 0; i < 4; i++) { float d0 = v[i] - mean; sq += d0 * d0; }
    red[tid] = sq; __syncthreads();
    for (int o = 128; o > 0; o >>= 1) { if (tid < o) red[tid] += red[tid + o]; __syncthreads(); }
    float rstd = rsqrtf(red[0] * (1.f / D) + 1e-5f);
    #pragma unroll
    for (int i = 0; i < 4; i++) {
        int c = tid + 256 * i;
        float y = (v[i] - mean) * rstd * w[c] + b[c];
        g_y[(ll)row * D + c] = __float2half_rn(y);
    }
}

// ---------------- y_len tail ----------------
__global__ void ylen_k(float* __restrict__ out, const int* __restrict__ x_len, ll out_size) {
    int i = threadIdx.x;
    if (i < Bn) {
        ll pos = (ll)NTOK * D + i;
        if (pos < out_size) {
            int yl = (x_len[i] + 1) / 2;
            yl = (yl + 1) / 2;
            out[pos] = (float)yl;
        }
    }
}

// ---------------- host launcher ----------------
extern "C" void kernel_launch(void* const* d_in, const int* in_sizes, int n_in,
                              void* d_out, int out_size) {
    const float* x        = (const float*)d_in[0];
    const int*   x_len    = (const int*)  d_in[1];
    const float* conv1_w  = (const float*)d_in[2];
    const float* conv1_b  = (const float*)d_in[3];
    const float* conv2_w  = (const float*)d_in[4];
    const float* conv2_b  = (const float*)d_in[5];
    const float* attn_ln_w= (const float*)d_in[6];
    const float* attn_ln_b= (const float*)d_in[7];
    const float* q_w      = (const float*)d_in[8];
    const float* q_b      = (const float*)d_in[9];
    const float* k_w      = (const float*)d_in[10];
    const float* v_w      = (const float*)d_in[11];
    const float* v_b      = (const float*)d_in[12];
    const float* out_w    = (const float*)d_in[13];
    const float* out_b    = (const float*)d_in[14];
    const float* mlp_ln_w = (const float*)d_in[15];
    const float* mlp_ln_b = (const float*)d_in[16];
    const float* mlp1_w   = (const float*)d_in[17];
    const float* mlp1_b   = (const float*)d_in[18];
    const float* mlp2_w   = (const float*)d_in[19];
    const float* mlp2_b   = (const float*)d_in[20];

    cudaFuncSetAttribute(gemm_tc, cudaFuncAttributeMaxDynamicSharedMemorySize, SMEM_TOT);
    cudaFuncSetAttribute(attn_k,  cudaFuncAttributeMaxDynamicSharedMemorySize, FSM_BYTES);

    #define SYM(p, s) do { void* _t; cudaGetSymbolAddress(&_t, s); p = (decltype(p))_t; } while (0)
    float *xs;
    SYM(xs, g_x);
    half *ph1, *pc1, *pc2, *pwq, *pwk, *pwv, *pwo, *pw1, *pw2;
    half *pcol, *py, *pq, *pk, *pvt, *pm1, *po;
    SYM(ph1, g_h1);
    SYM(pc1, c1w); SYM(pc2, c2w);
    SYM(pwq, wq); SYM(pwk, wk); SYM(pwv, wv); SYM(pwo, wo);
    SYM(pw1, w1); SYM(pw2, w2);
    SYM(pcol, g_col); SYM(py, g_y); SYM(pq, g_q); SYM(pk, g_k);
    SYM(pvt, g_vt); SYM(pm1, g_m1); SYM(po, g_o);

    auto cvt = [&](const float* in, half* out, ll n) {
        cvt_k<<<(int)((n / 8 + 255) / 256), 256>>>(in, out, n);
    };
    cvt(conv1_w, pc1, (ll)D * 384);
    cvt_c2_k<<<(int)(((ll)D * 3072 + 255) / 256), 256>>>(conv2_w, pc2);
    cvt(q_w,   pwq, (ll)Ldim * D * D);
    cvt(k_w,   pwk, (ll)Ldim * D * D);
    cvt(v_w,   pwv, (ll)Ldim * D * D);
    cvt(out_w, pwo, (ll)Ldim * D * D);
    cvt(mlp1_w, pw1, (ll)Ldim * Fdim * D);
    cvt(mlp2_w, pw2, (ll)Ldim * Fdim * D);

    auto gemm = [&](const half* A, const half* B,
                    float* C, half* Cs, const float* bias,
                    int M, int N, int K, int lda, int ldb, int ldc,
                    int nz, int zDiv,
                    ll sAo, ll sAi, ll sBo, ll sBi, ll sCo, ll sCi,
                    int biasMode, int addC, int act, int transStore,
                    int outF32, int outHalf, const float* Cin = 0, int aConv = 0) {
        GemmP p = {};
        p.A = A; p.B = B;
        p.C = C; p.Cs = Cs; p.Cin = Cin; p.bias = bias;
        p.K = K; p.lda = lda; p.ldb = ldb; p.ldc = ldc;
        p.zDiv = zDiv;
        p.sAo = sAo; p.sAi = sAi; p.sBo = sBo; p.sBi = sBi; p.sCo = sCo; p.sCi = sCi;
        p.biasMode = biasMode; p.addC = addC; p.act = act;
        p.transStore = transStore;
        p.outF32 = outF32; p.outHalf = outHalf; p.aConv = aConv;
        p.qkvZ = 0;
        dim3 g(N / 256, M / 128, nz);
        gemm_tc<<<g, 512, SMEM_TOT>>>(p);
    };

    const ll SD = (ll)S * D;

    // conv1: im2col + GEMM -> g_h1 fp16
    im2col1_k<<<(Bn * T1 * 384 + 255) / 256, 256>>>(x);
    gemm(pcol, pc1, 0, ph1, conv1_b,
         T1, 1024, 384, 384, 384, D,
         Bn, 1, (ll)T1 * 384, 0, 0, 0, (ll)T1 * D, 0,
         1, 0, 1, 0, 0, 1);

    // conv2: direct read from g_h1 (kk-major K, zero-fill boundary) -> g_x fp32
    gemm(ph1, pc2, xs, 0, conv2_b,
         S, 1024, 3072, 1024, 3072, D,
         Bn, 1, (ll)T1 * D, 0, 0, 0, SD, 0,
         1, 0, 1, 0, 1, 0, 0, 1);

    for (int l = 0; l < 6; l++) {
        const float* aw = attn_ln_w + l * D;  const float* ab = attn_ln_b + l * D;
        const float* qb = q_b + l * D;
        const float* vb = v_b + l * D;
        const float* ob = out_b + l * D;
        const float* mw = mlp_ln_w + l * D;   const float* mb2 = mlp_ln_b + l * D;
        const float* b1 = mlp1_b + l * Fdim;
        const float* b2 = mlp2_b + l * D;
        ll wOff = (ll)l * D * D;
        ll mOff = (ll)l * Fdim * D;

        ln_k<<<NTOK, 256>>>(xs, aw, ab);

        // fused qkv: one launch, grid.z selects q/k/v (uniform per-CTA epilogue)
        {
            GemmP p = {};
            p.A = py;
            p.B = pwq + wOff; p.Bk = pwk + wOff; p.Bv = pwv + wOff;
            p.Qd = pq; p.Kd = pk; p.Vd = pvt;
            p.bias = qb; p.bias2 = vb;
            p.K = D; p.lda = D; p.ldb = D; p.ldc = D;
            p.zDiv = 1;
            p.qkvZ = 1;
            dim3 g(D / 256, NTOK / 128, 3);
            gemm_tc<<<g, 512, SMEM_TOT>>>(p);
        }

        // fused flash attention -> g_o fp16
        attn_k<<<dim3(S / 128, Bn * H), 256, FSM_BYTES>>>(x_len);

        // out projection + residual
        gemm(po, pwo + wOff, xs, 0, ob,
             NTOK, D, D, D, D, D, 1, 1, 0,0,0,0,0,0, 1, 1, 0, 0, 1, 0);

        // MLP (last layer's mlp2 writes directly to d_out)
        ln_k<<<NTOK, 256>>>(xs, mw, mb2);
        gemm(py, pw1 + mOff, 0, pm1, b1,
             NTOK, Fdim, D, D, D, Fdim, 1, 1, 0,0,0,0,0,0, 1, 0, 1, 0, 0, 1);
        if (l < 5) {
            gemm(pm1, pw2 + mOff, xs, 0, b2,
                 NTOK, D, Fdim, Fdim, Fdim, D, 1, 1, 0,0,0,0,0,0, 1, 1, 0, 0, 1, 0);
        } else {
            gemm(pm1, pw2 + mOff, (float*)d_out, 0, b2,
                 NTOK, D, Fdim, Fdim, Fdim, D, 1, 1, 0,0,0,0,0,0, 1, 1, 0, 0, 1, 0, xs);
        }
    }

    ylen_k<<<1, 32>>>((float*)d_out, x_len, (ll)out_size);
}

// round 15
// speedup vs baseline: 1.0558x; 1.0558x over previous
#include <cuda_runtime.h>
#include <cuda_fp16.h>
#include <math.h>

typedef long long ll;
typedef unsigned u32;

#define Bn 8
#define NMELS 128
#define TIN 4096
#define T1 2048
#define S 1024
#define D 1024
#define H 8
#define DH 128
#define Fdim 4096
#define NTOK (Bn*S)
#define Ldim 6

// ---------------- fp32 scratch ----------------
__device__ float g_x [(size_t)NTOK*D];             // residual stream

// ---------------- fp16 buffers ----------------
__device__ __align__(256) half g_h1[(size_t)Bn*T1*D];   // conv1 out [b][t][d]
__device__ __align__(256) half c1w[(size_t)D*384];
__device__ __align__(256) half c2w[(size_t)D*3072];     // reordered: [d][kk*1024+i]
__device__ __align__(256) half wq[(size_t)Ldim*D*D];
__device__ __align__(256) half wk[(size_t)Ldim*D*D];
__device__ __align__(256) half wv[(size_t)Ldim*D*D];
__device__ __align__(256) half wo[(size_t)Ldim*D*D];
__device__ __align__(256) half w1[(size_t)Ldim*Fdim*D];
__device__ __align__(256) half w2[(size_t)Ldim*Fdim*D];
__device__ __align__(256) half g_col[(size_t)Bn*T1*384];
__device__ __align__(256) half g_y [(size_t)NTOK*D];
__device__ __align__(256) half g_q [(size_t)NTOK*D];
__device__ __align__(256) half g_k [(size_t)NTOK*D];
__device__ __align__(256) half g_vt[(size_t)D*NTOK];
__device__ __align__(256) half g_m1[(size_t)NTOK*Fdim];
__device__ __align__(256) half g_o [(size_t)NTOK*D];

// ---------------- helpers ----------------
__device__ __forceinline__ float gelu_exact(float v) {
    return 0.5f * v * (1.0f + erff(v * 0.70710678118654752f));
}
__device__ __forceinline__ void mma_fp16(float* d, const u32* a, const u32* b) {
    asm volatile(
        "mma.sync.aligned.m16n8k16.row.col.f32.f16.f16.f32 "
        "{%0,%1,%2,%3}, {%4,%5,%6,%7}, {%8,%9}, {%0,%1,%2,%3};\n"
        : "+f"(d[0]), "+f"(d[1]), "+f"(d[2]), "+f"(d[3])
        : "r"(a[0]), "r"(a[1]), "r"(a[2]), "r"(a[3]), "r"(b[0]), "r"(b[1]));
}
__device__ __forceinline__ void ldsm4(u32* r, u32 addr) {
    asm volatile("ldmatrix.sync.aligned.m8n8.x4.shared.b16 {%0,%1,%2,%3}, [%4];\n"
        : "=r"(r[0]), "=r"(r[1]), "=r"(r[2]), "=r"(r[3]) : "r"(addr));
}
__device__ __forceinline__ void cpa16(u32 dst, const void* src) {
    asm volatile("cp.async.cg.shared.global [%0], [%1], 16;\n" :: "r"(dst), "l"(src));
}
__device__ __forceinline__ void cpa16p(u32 dst, const void* src, int pred) {
    int sz = pred ? 16 : 0;
    asm volatile("cp.async.cg.shared.global [%0], [%1], 16, %2;\n" :: "r"(dst), "l"(src), "r"(sz));
}
__device__ __forceinline__ u32 packh2(float lo, float hi) {
    __half2 h = __floats2half2_rn(lo, hi);
    return *(u32*)&h;
}

// ---------------- fp16 tensor-core GEMM (16 warps, 128x128 tile, KC=64, 3-stage) ----------------
// C[M,N] = A[M,K] * B[N,K]^T
#define KC 64
#define NSTG 3
#define PADR 72
#define TILE_E (128*PADR)
#define TILE_B2 (TILE_E*2)
#define STG_B  (2*TILE_B2)
#define SMEM_TOT (NSTG*STG_B)        // 110592

struct GemmP {
    const half *A, *B;
    const half *Bk, *Bv;     // qkvZ weight pointers for z=1,2
    float* C; half *Cs;
    half *Qd, *Kd, *Vd;      // qkvZ outputs
    const float* Cin;
    const float* bias;
    const float* bias2;      // qkvZ: v bias
    int K, lda, ldb, ldc;
    int zDiv;
    ll sAo, sAi, sBo, sBi, sCo, sCi;
    int biasMode;   // 0 none, 1 per-col(n), 2 per-row(m)
    int addC;
    int act;        // 0 none, 1 exact GELU, 2 RoPE+scale
    int transStore;
    int outF32, outHalf;
    int aConv;
    int qkvZ;       // grid.z selects q/k/v
};

__device__ __forceinline__ void rope2(float& v0, float& v1, int m, int cB) {
    int s = m & (S - 1);
    int j = (cB & 127) >> 1;
    float freq = powf(10000.f, -(float)(2 * j) * (1.f / 128.f));
    float ang = (float)s * freq;
    float cc, ss; sincosf(ang, &ss, &cc);
    const float sc = 0.29730177875068026f;  // 128^-0.25
    float r0 = (v0 * cc - v1 * ss) * sc;
    float r1 = (v0 * ss + v1 * cc) * sc;
    v0 = r0; v1 = r1;
}

__global__ __launch_bounds__(512, 1) void gemm_tc(GemmP p) {
    extern __shared__ __align__(16) half sm[];
    int z = blockIdx.z;
    ll offA = 0, offB = 0, offC = 0;
    const half* A = p.A;
    const half* B = p.B;
    if (p.qkvZ) {
        B = (z == 0) ? p.B : (z == 1) ? p.Bk : p.Bv;
    } else {
        offA = (ll)(z / p.zDiv) * p.sAo + (ll)(z % p.zDiv) * p.sAi;
        offB = (ll)(z / p.zDiv) * p.sBo + (ll)(z % p.zDiv) * p.sBi;
        offC = (ll)(z / p.zDiv) * p.sCo + (ll)(z % p.zDiv) * p.sCi;
        A += offA; B += offB;
    }

    int m0 = blockIdx.y * 128, n0 = blockIdx.x * 128;
    int tid = threadIdx.x, lane = tid & 31, wid = tid >> 5;
    int wm = (wid & 3) * 32, wn = (wid >> 2) * 32;
    u32 smu = (u32)__cvta_generic_to_shared(sm);

    float acc[2][4][4];
    #pragma unroll
    for (int a = 0; a < 2; a++)
        #pragma unroll
        for (int b = 0; b < 4; b++)
            #pragma unroll
            for (int c = 0; c < 4; c++) acc[a][b][c] = 0.f;

    int ldRow = tid >> 3;
    int ldCC  = (tid & 7) * 8;

    auto issue = [&](int c) {
        u32 base = smu + (u32)(c % NSTG) * STG_B;
        int k0 = c * KC;
        #pragma unroll
        for (int hh = 0; hh < 2; hh++) {
            int row = ldRow + hh * 64;
            u32 so = (u32)(row * PADR + ldCC) * 2;
            if (p.aConv) {
                int kk = k0 >> 10;
                int i0 = (k0 & 1023) + ldCC;
                int pos = 2 * (m0 + row) + kk - 1;
                const half* src = A + (ll)(pos < 0 ? 0 : pos) * 1024 + i0;
                cpa16p(base + so, src, pos >= 0);
            } else {
                cpa16(base + so, A + (ll)(m0 + row) * p.lda + k0 + ldCC);
            }
            cpa16(base + TILE_B2 + so, B + (ll)(n0 + row) * p.ldb + k0 + ldCC);
        }
        asm volatile("cp.async.commit_group;" ::: "memory");
    };

    int nch = p.K / KC;
    issue(0);
    if (nch > 1) issue(1);

    for (int c = 0; c < nch; c++) {
        if (c + 1 < nch) asm volatile("cp.async.wait_group 1;" ::: "memory");
        else             asm volatile("cp.async.wait_group 0;" ::: "memory");
        __syncthreads();
        if (c + 2 < nch) issue(c + 2);

        u32 aB = smu + (u32)(c % NSTG) * STG_B;
        u32 bB = aB + TILE_B2;

        #pragma unroll
        for (int ks = 0; ks < 4; ks++) {
            u32 ar[2][4], br[4][2];
            #pragma unroll
            for (int mi = 0; mi < 2; mi++) {
                int row = wm + mi * 16 + (lane & 15);
                int col = ks * 16 + (lane >> 4) * 8;
                ldsm4(ar[mi], aB + (u32)(row * PADR + col) * 2);
            }
            #pragma unroll
            for (int nj = 0; nj < 2; nj++) {
                int g = lane >> 3;
                int row = wn + nj * 16 + ((g >> 1) << 3) + (lane & 7);
                int col = ks * 16 + ((g & 1) << 3);
                u32 t[4];
                ldsm4(t, bB + (u32)(row * PADR + col) * 2);
                br[nj*2][0] = t[0]; br[nj*2][1] = t[1];
                br[nj*2+1][0] = t[2]; br[nj*2+1][1] = t[3];
            }
            #pragma unroll
            for (int mi = 0; mi < 2; mi++)
                #pragma unroll
                for (int nf = 0; nf < 4; nf++)
                    mma_fp16(acc[mi][nf], ar[mi], br[nf]);
        }
    }

    float* Cp = p.C  ? p.C  + offC : nullptr;
    half* Csp = p.Cs ? p.Cs + offC : nullptr;
    const float* Rp = p.Cin ? p.Cin + offC : Cp;
    #pragma unroll
    for (int mi = 0; mi < 2; mi++)
        #pragma unroll
        for (int nf = 0; nf < 4; nf++) {
            int rB = m0 + wm + mi * 16 + (lane >> 2);
            int cB = n0 + wn + nf * 8 + (lane & 3) * 2;
            #pragma unroll
            for (int pe = 0; pe < 2; pe++) {
                int m = rB + pe * 8;
                float v0 = acc[mi][nf][pe * 2 + 0];
                float v1 = acc[mi][nf][pe * 2 + 1];

                if (p.qkvZ) {
                    int z2 = blockIdx.z;
                    if (z2 == 0) {
                        v0 += p.bias[cB]; v1 += p.bias[cB + 1];
                        rope2(v0, v1, m, cB);
                        *(u32*)&p.Qd[(ll)m * D + cB] = packh2(v0, v1);
                    } else if (z2 == 1) {
                        rope2(v0, v1, m, cB);
                        *(u32*)&p.Kd[(ll)m * D + cB] = packh2(v0, v1);
                    } else {
                        v0 += p.bias2[cB]; v1 += p.bias2[cB + 1];
                        p.Vd[(ll)cB * NTOK + m]       = __float2half_rn(v0);
                        p.Vd[(ll)(cB + 1) * NTOK + m] = __float2half_rn(v1);
                    }
                    continue;
                }

                if (p.biasMode == 1) { v0 += p.bias[cB]; v1 += p.bias[cB + 1]; }
                else if (p.biasMode == 2) { float bb = p.bias[m]; v0 += bb; v1 += bb; }
                if (p.act == 1) { v0 = gelu_exact(v0); v1 = gelu_exact(v1); }
                else if (p.act == 2) rope2(v0, v1, m, cB);

                if (!p.transStore) {
                    ll off0 = (ll)m * p.ldc + cB;
                    if (p.outF32) {
                        float w0 = v0, w1 = v1;
                        if (p.addC) {
                            float2 o = *(const float2*)&Rp[off0];
                            w0 += o.x; w1 += o.y;
                        }
                        *(float2*)&Cp[off0] = make_float2(w0, w1);
                    }
                    if (p.outHalf) *(u32*)&Csp[off0] = packh2(v0, v1);
                } else {
                    ll off0 = (ll)cB * p.ldc + m;
                    ll off1 = off0 + p.ldc;
                    if (p.outF32) {
                        float w0 = v0, w1 = v1;
                        if (p.addC) { w0 += Rp[off0]; w1 += Rp[off1]; }
                        Cp[off0] = w0; Cp[off1] = w1;
                    }
                    if (p.outHalf) {
                        Csp[off0] = __float2half_rn(v0);
                        Csp[off1] = __float2half_rn(v1);
                    }
                }
            }
        }
}

// ---------------- fused flash attention (K-prefetch pipelined) ----------------
#define FP2 136
#define FSM_BYTES ((128+128+128)*FP2*2)    // 104448

__global__ __launch_bounds__(256) void attn_k(const int* __restrict__ x_len) {
    extern __shared__ __align__(16) half fsm[];
    int tid = threadIdx.x, lane = tid & 31, wid = tid >> 5;
    int bh = blockIdx.y, b = bh >> 3, h = bh & 7;
    int m0 = blockIdx.x * 128;
    int wm = wid * 16;
    u32 smu = (u32)__cvta_generic_to_shared(fsm);
    u32 sQ = smu;
    u32 sK = smu + (u32)(128 * FP2) * 2;
    u32 sV = sK + (u32)(128 * FP2) * 2;

    const half* qp = g_q + ((ll)(b * S + m0)) * D + h * 128;
    const half* kp = g_k + ((ll)b * S) * D + h * 128;
    const half* vp = g_vt + ((ll)(h * 128)) * NTOK + (ll)b * S;

    // Q group
    #pragma unroll
    for (int i = 0; i < 8; i++) {
        int idx = tid + 256 * i, row = idx >> 4, ch = idx & 15;
        cpa16(sQ + (u32)(row * FP2 + ch * 8) * 2, qp + (ll)row * D + ch * 8);
    }
    asm volatile("cp.async.commit_group;" ::: "memory");
    // K(0) prefetch group
    #pragma unroll
    for (int i = 0; i < 8; i++) {
        int idx = tid + 256 * i, row = idx >> 4, ch = idx & 15;
        cpa16(sK + (u32)(row * FP2 + ch * 8) * 2, kp + (ll)row * D + ch * 8);
    }
    asm volatile("cp.async.commit_group;" ::: "memory");

    int xl = x_len[b];
    int quad = lane >> 2, qi = lane & 3;
    float mrow[2] = {-1e30f, -1e30f}, lrow[2] = {0.f, 0.f};
    float oacc[16][4];
    #pragma unroll
    for (int nt = 0; nt < 16; nt++)
        #pragma unroll
        for (int e = 0; e < 4; e++) oacc[nt][e] = 0.f;

    for (int kv0 = 0; kv0 < S; kv0 += 128) {
        if (kv0) __syncthreads();   // sV reads from previous PV done
        // V(i) group
        #pragma unroll
        for (int i = 0; i < 8; i++) {
            int idx = tid + 256 * i, row = idx >> 4, ch = idx & 15;
            cpa16(sV + (u32)(row * FP2 + ch * 8) * 2, vp + (ll)row * NTOK + kv0 + ch * 8);
        }
        asm volatile("cp.async.commit_group;" ::: "memory");
        // wait K(i) (V(i) stays in flight)
        asm volatile("cp.async.wait_group 1;" ::: "memory");
        __syncthreads();

        // S = Q @ K^T
        float sacc[16][4];
        #pragma unroll
        for (int nt = 0; nt < 16; nt++)
            #pragma unroll
            for (int e = 0; e < 4; e++) sacc[nt][e] = 0.f;

        #pragma unroll
        for (int ks = 0; ks < 8; ks++) {
            u32 aq[4];
            ldsm4(aq, sQ + (u32)((wm + (lane & 15)) * FP2 + ks * 16 + (lane >> 4) * 8) * 2);
            #pragma unroll
            for (int njp = 0; njp < 8; njp++) {
                int g = lane >> 3;
                int row = njp * 16 + ((g >> 1) << 3) + (lane & 7);
                int col = ks * 16 + ((g & 1) << 3);
                u32 t[4];
                ldsm4(t, sK + (u32)(row * FP2 + col) * 2);
                u32 b0[2] = {t[0], t[1]}, b1[2] = {t[2], t[3]};
                mma_fp16(sacc[njp*2],   aq, b0);
                mma_fp16(sacc[njp*2+1], aq, b1);
            }
        }
        __syncthreads();            // all warps done reading sK
        int hasNext = (kv0 + 128 < S);
        if (hasNext) {              // K(i+1) prefetch into freed sK
            #pragma unroll
            for (int i = 0; i < 8; i++) {
                int idx = tid + 256 * i, row = idx >> 4, ch = idx & 15;
                cpa16(sK + (u32)(row * FP2 + ch * 8) * 2, kp + (ll)(kv0 + 128 + row) * D + ch * 8);
            }
            asm volatile("cp.async.commit_group;" ::: "memory");
        }

        // mask + online softmax (overlaps V(i) completion and K(i+1) flight)
        float rmax[2] = {-1e30f, -1e30f};
        #pragma unroll
        for (int nt = 0; nt < 16; nt++)
            #pragma unroll
            for (int e = 0; e < 4; e++) {
                int col = kv0 + nt * 8 + qi * 2 + (e & 1);
                float v = sacc[nt][e] + ((4 * col + 3 < xl) ? 0.f : -1e10f);
                sacc[nt][e] = v;
                rmax[e >> 1] = fmaxf(rmax[e >> 1], v);
            }
        #pragma unroll
        for (int s2 = 1; s2 < 4; s2 <<= 1) {
            rmax[0] = fmaxf(rmax[0], __shfl_xor_sync(0xffffffff, rmax[0], s2));
            rmax[1] = fmaxf(rmax[1], __shfl_xor_sync(0xffffffff, rmax[1], s2));
        }
        float mn0 = fmaxf(mrow[0], rmax[0]), mn1 = fmaxf(mrow[1], rmax[1]);
        float sc0 = expf(mrow[0] - mn0), sc1 = expf(mrow[1] - mn1);
        float rsum[2] = {0.f, 0.f};
        #pragma unroll
        for (int nt = 0; nt < 16; nt++)
            #pragma unroll
            for (int e = 0; e < 4; e++) {
                float v = expf(sacc[nt][e] - ((e >> 1) ? mn1 : mn0));
                sacc[nt][e] = v;
                rsum[e >> 1] += v;
            }
        #pragma unroll
        for (int s2 = 1; s2 < 4; s2 <<= 1) {
            rsum[0] += __shfl_xor_sync(0xffffffff, rsum[0], s2);
            rsum[1] += __shfl_xor_sync(0xffffffff, rsum[1], s2);
        }
        lrow[0] = lrow[0] * sc0 + rsum[0];
        lrow[1] = lrow[1] * sc1 + rsum[1];
        mrow[0] = mn0; mrow[1] = mn1;
        #pragma unroll
        for (int nt = 0; nt < 16; nt++) {
            oacc[nt][0] *= sc0; oacc[nt][1] *= sc0;
            oacc[nt][2] *= sc1; oacc[nt][3] *= sc1;
        }

        // wait V(i): if K(i+1) issued it may stay in flight (groups retire in order)
        if (hasNext) asm volatile("cp.async.wait_group 1;" ::: "memory");
        else         asm volatile("cp.async.wait_group 0;" ::: "memory");
        __syncthreads();

        // O += P @ V
        #pragma unroll
        for (int j = 0; j < 8; j++) {
            u32 af[4];
            af[0] = packh2(sacc[2*j][0],   sacc[2*j][1]);
            af[1] = packh2(sacc[2*j][2],   sacc[2*j][3]);
            af[2] = packh2(sacc[2*j+1][0], sacc[2*j+1][1]);
            af[3] = packh2(sacc[2*j+1][2], sacc[2*j+1][3]);
            #pragma unroll
            for (int njp = 0; njp < 8; njp++) {
                int g = lane >> 3;
                int row = njp * 16 + ((g >> 1) << 3) + (lane & 7);
                int col = j * 16 + ((g & 1) << 3);
                u32 t[4];
                ldsm4(t, sV + (u32)(row * FP2 + col) * 2);
                u32 b0[2] = {t[0], t[1]}, b1[2] = {t[2], t[3]};
                mma_fp16(oacc[njp*2],   af, b0);
                mma_fp16(oacc[njp*2+1], af, b1);
            }
        }
    }

    float inv0 = 1.f / lrow[0], inv1 = 1.f / lrow[1];
    half* op = g_o + ((ll)(b * S + m0 + wm)) * D + h * 128;
    #pragma unroll
    for (int nt = 0; nt < 16; nt++)
        #pragma unroll
        for (int pe = 0; pe < 2; pe++) {
            int row = quad + pe * 8;
            float iv = pe ? inv1 : inv0;
            u32 pk = packh2(oacc[nt][pe*2] * iv, oacc[nt][pe*2+1] * iv);
            *(u32*)&op[(ll)row * D + nt * 8 + qi * 2] = pk;
        }
}

// ---------------- weight converts (8 elems/thread, packed 16B store) ----------------
__global__ void cvt_k(const float* __restrict__ in, half* __restrict__ out, ll n) {
    ll i = ((ll)blockIdx.x * 256 + threadIdx.x) * 8;
    if (i >= n) return;
    float4 a = *(const float4*)&in[i];
    float4 b = *(const float4*)&in[i + 4];
    uint4 o;
    o.x = packh2(a.x, a.y);
    o.y = packh2(a.z, a.w);
    o.z = packh2(b.x, b.y);
    o.w = packh2(b.z, b.w);
    *(uint4*)&out[i] = o;
}
// conv2 weights: out[d][kk*1024+i] = in[d][i*3+kk]
__global__ void cvt_c2_k(const float* __restrict__ in, half* __restrict__ out) {
    ll idx = (ll)blockIdx.x * 256 + threadIdx.x;
    if (idx >= (ll)D * 3072) return;
    int rp = (int)(idx % 3072);
    int d  = (int)(idx / 3072);
    int kk = rp >> 10, i = rp & 1023;
    out[idx] = __float2half_rn(in[(ll)d * 3072 + i * 3 + kk]);
}

// ---------------- im2col for conv1 ----------------
__global__ void im2col1_k(const float* __restrict__ x) {
    int idx = blockIdx.x * 256 + threadIdx.x;
    const int total = Bn * T1 * 384;
    if (idx >= total) return;
    int r = idx % 384;
    int t = (idx / 384) % T1;
    int b = idx / (384 * T1);
    int i = r / 3, kk = r % 3;
    int pos = 2 * t + kk - 1;
    float v = (pos >= 0 && pos < TIN) ? x[((ll)b * NMELS + i) * TIN + pos] : 0.f;
    g_col[idx] = __float2half_rn(v);
}

// ---------------- LayerNorm -> fp16 (shuffle reductions, vectorized I/O) ----------------
__global__ void ln_k(const float* __restrict__ x,
                     const float* __restrict__ w, const float* __restrict__ b) {
    int row = blockIdx.x;
    int tid = threadIdx.x, lane = tid & 31, wid = tid >> 5;
    const float* xr = x + (ll)row * D;
    __shared__ float red[8];
    __shared__ float bc;
    float4 v4 = *(const float4*)&xr[tid * 4];
    float v[4] = {v4.x, v4.y, v4.z, v4.w};

    float s = v[0] + v[1] + v[2] + v[3];
    #pragma unroll
    for (int o = 16; o > 0; o >>= 1) s += __shfl_xor_sync(0xffffffff, s, o);
    if (lane == 0) red[wid] = s;
    __syncthreads();
    if (tid < 8) {
        float t = red[tid];
        #pragma unroll
        for (int o = 4; o > 0; o >>= 1) t += __shfl_xor_sync(0xff, t, o);
        if (tid == 0) bc = t;
    }
    __syncthreads();
    float mean = bc * (1.f / D);

    float sq = 0.f;
    #pragma unroll
    for (int i = 0; i < 4; i++) { float d0 = v[i] - mean; sq += d0 * d0; }
    #pragma unroll
    for (int o = 16; o > 0; o >>= 1) sq += __shfl_xor_sync(0xffffffff, sq, o);
    if (lane == 0) red[wid] = sq;
    __syncthreads();
    if (tid < 8) {
        float t = red[tid];
        #pragma unroll
        for (int o = 4; o > 0; o >>= 1) t += __shfl_xor_sync(0xff, t, o);
        if (tid == 0) bc = t;
    }
    __syncthreads();
    float rstd = rsqrtf(bc * (1.f / D) + 1e-5f);

    int c = tid * 4;
    float4 w4 = *(const float4*)&w[c];
    float4 b4 = *(const float4*)&b[c];
    float y0 = (v[0] - mean) * rstd * w4.x + b4.x;
    float y1 = (v[1] - mean) * rstd * w4.y + b4.y;
    float y2 = (v[2] - mean) * rstd * w4.z + b4.z;
    float y3 = (v[3] - mean) * rstd * w4.w + b4.w;
    uint2 pk = make_uint2(packh2(y0, y1), packh2(y2, y3));
    *(uint2*)&g_y[(ll)row * D + c] = pk;
}

// ---------------- y_len tail ----------------
__global__ void ylen_k(float* __restrict__ out, const int* __restrict__ x_len, ll out_size) {
    int i = threadIdx.x;
    if (i < Bn) {
        ll pos = (ll)NTOK * D + i;
        if (pos < out_size) {
            int yl = (x_len[i] + 1) / 2;
            yl = (yl + 1) / 2;
            out[pos] = (float)yl;
        }
    }
}

// ---------------- host launcher ----------------
extern "C" void kernel_launch(void* const* d_in, const int* in_sizes, int n_in,
                              void* d_out, int out_size) {
    const float* x        = (const float*)d_in[0];
    const int*   x_len    = (const int*)  d_in[1];
    const float* conv1_w  = (const float*)d_in[2];
    const float* conv1_b  = (const float*)d_in[3];
    const float* conv2_w  = (const float*)d_in[4];
    const float* conv2_b  = (const float*)d_in[5];
    const float* attn_ln_w= (const float*)d_in[6];
    const float* attn_ln_b= (const float*)d_in[7];
    const float* q_w      = (const float*)d_in[8];
    const float* q_b      = (const float*)d_in[9];
    const float* k_w      = (const float*)d_in[10];
    const float* v_w      = (const float*)d_in[11];
    const float* v_b      = (const float*)d_in[12];
    const float* out_w    = (const float*)d_in[13];
    const float* out_b    = (const float*)d_in[14];
    const float* mlp_ln_w = (const float*)d_in[15];
    const float* mlp_ln_b = (const float*)d_in[16];
    const float* mlp1_w   = (const float*)d_in[17];
    const float* mlp1_b   = (const float*)d_in[18];
    const float* mlp2_w   = (const float*)d_in[19];
    const float* mlp2_b   = (const float*)d_in[20];

    cudaFuncSetAttribute(gemm_tc, cudaFuncAttributeMaxDynamicSharedMemorySize, SMEM_TOT);
    cudaFuncSetAttribute(attn_k,  cudaFuncAttributeMaxDynamicSharedMemorySize, FSM_BYTES);

    #define SYM(p, s) do { void* _t; cudaGetSymbolAddress(&_t, s); p = (decltype(p))_t; } while (0)
    float *xs;
    SYM(xs, g_x);
    half *ph1, *pc1, *pc2, *pwq, *pwk, *pwv, *pwo, *pw1, *pw2;
    half *pcol, *py, *pq, *pk, *pvt, *pm1, *po;
    SYM(ph1, g_h1);
    SYM(pc1, c1w); SYM(pc2, c2w);
    SYM(pwq, wq); SYM(pwk, wk); SYM(pwv, wv); SYM(pwo, wo);
    SYM(pw1, w1); SYM(pw2, w2);
    SYM(pcol, g_col); SYM(py, g_y); SYM(pq, g_q); SYM(pk, g_k);
    SYM(pvt, g_vt); SYM(pm1, g_m1); SYM(po, g_o);

    auto cvt = [&](const float* in, half* out, ll n) {
        cvt_k<<<(int)((n / 8 + 255) / 256), 256>>>(in, out, n);
    };
    cvt(conv1_w, pc1, (ll)D * 384);
    cvt_c2_k<<<(int)(((ll)D * 3072 + 255) / 256), 256>>>(conv2_w, pc2);
    cvt(q_w,   pwq, (ll)Ldim * D * D);
    cvt(k_w,   pwk, (ll)Ldim * D * D);
    cvt(v_w,   pwv, (ll)Ldim * D * D);
    cvt(out_w, pwo, (ll)Ldim * D * D);
    cvt(mlp1_w, pw1, (ll)Ldim * Fdim * D);
    cvt(mlp2_w, pw2, (ll)Ldim * Fdim * D);

    auto gemm = [&](const half* A, const half* B,
                    float* C, half* Cs, const float* bias,
                    int M, int N, int K, int lda, int ldb, int ldc,
                    int nz, int zDiv,
                    ll sAo, ll sAi, ll sBo, ll sBi, ll sCo, ll sCi,
                    int biasMode, int addC, int act, int transStore,
                    int outF32, int outHalf, const float* Cin = 0, int aConv = 0) {
        GemmP p = {};
        p.A = A; p.B = B;
        p.C = C; p.Cs = Cs; p.Cin = Cin; p.bias = bias;
        p.K = K; p.lda = lda; p.ldb = ldb; p.ldc = ldc;
        p.zDiv = zDiv;
        p.sAo = sAo; p.sAi = sAi; p.sBo = sBo; p.sBi = sBi; p.sCo = sCo; p.sCi = sCi;
        p.biasMode = biasMode; p.addC = addC; p.act = act;
        p.transStore = transStore;
        p.outF32 = outF32; p.outHalf = outHalf; p.aConv = aConv;
        p.qkvZ = 0;
        dim3 g(N / 128, M / 128, nz);
        gemm_tc<<<g, 512, SMEM_TOT>>>(p);
    };

    const ll SD = (ll)S * D;

    // conv1: im2col + GEMM -> g_h1 fp16
    im2col1_k<<<(Bn * T1 * 384 + 255) / 256, 256>>>(x);
    gemm(pcol, pc1, 0, ph1, conv1_b,
         T1, 1024, 384, 384, 384, D,
         Bn, 1, (ll)T1 * 384, 0, 0, 0, (ll)T1 * D, 0,
         1, 0, 1, 0, 0, 1);

    // conv2: direct read from g_h1 (kk-major K, zero-fill boundary) -> g_x fp32
    gemm(ph1, pc2, xs, 0, conv2_b,
         S, 1024, 3072, 1024, 3072, D,
         Bn, 1, (ll)T1 * D, 0, 0, 0, SD, 0,
         1, 0, 1, 0, 1, 0, 0, 1);

    for (int l = 0; l < 6; l++) {
        const float* aw = attn_ln_w + l * D;  const float* ab = attn_ln_b + l * D;
        const float* qb = q_b + l * D;
        const float* vb = v_b + l * D;
        const float* ob = out_b + l * D;
        const float* mw = mlp_ln_w + l * D;   const float* mb2 = mlp_ln_b + l * D;
        const float* b1 = mlp1_b + l * Fdim;
        const float* b2 = mlp2_b + l * D;
        ll wOff = (ll)l * D * D;
        ll mOff = (ll)l * Fdim * D;

        ln_k<<<NTOK, 256>>>(xs, aw, ab);

        // fused qkv: one launch, grid.z selects q/k/v (uniform per-CTA epilogue)
        {
            GemmP p = {};
            p.A = py;
            p.B = pwq + wOff; p.Bk = pwk + wOff; p.Bv = pwv + wOff;
            p.Qd = pq; p.Kd = pk; p.Vd = pvt;
            p.bias = qb; p.bias2 = vb;
            p.K = D; p.lda = D; p.ldb = D; p.ldc = D;
            p.zDiv = 1;
            p.qkvZ = 1;
            dim3 g(D / 128, NTOK / 128, 3);
            gemm_tc<<<g, 512, SMEM_TOT>>>(p);
        }

        // fused flash attention -> g_o fp16
        attn_k<<<dim3(S / 128, Bn * H), 256, FSM_BYTES>>>(x_len);

        // out projection + residual
        gemm(po, pwo + wOff, xs, 0, ob,
             NTOK, D, D, D, D, D, 1, 1, 0,0,0,0,0,0, 1, 1, 0, 0, 1, 0);

        // MLP (last layer's mlp2 writes directly to d_out)
        ln_k<<<NTOK, 256>>>(xs, mw, mb2);
        gemm(py, pw1 + mOff, 0, pm1, b1,
             NTOK, Fdim, D, D, D, Fdim, 1, 1, 0,0,0,0,0,0, 1, 0, 1, 0, 0, 1);
        if (l < 5) {
            gemm(pm1, pw2 + mOff, xs, 0, b2,
                 NTOK, D, Fdim, Fdim, Fdim, D, 1, 1, 0,0,0,0,0,0, 1, 1, 0, 0, 1, 0);
        } else {
            gemm(pm1, pw2 + mOff, (float*)d_out, 0, b2,
                 NTOK, D, Fdim, Fdim, Fdim, D, 1, 1, 0,0,0,0,0,0, 1, 1, 0, 0, 1, 0, xs);
        }
    }

    ylen_k<<<1, 32>>>((float*)d_out, x_len, (ll)out_size);
}

// round 16
// speedup vs baseline: 1.0599x; 1.0038x over previous
#include <cuda_runtime.h>
#include <cuda_fp16.h>
#include <math.h>

typedef long long ll;
typedef unsigned u32;

#define Bn 8
#define NMELS 128
#define TIN 4096
#define T1 2048
#define S 1024
#define D 1024
#define H 8
#define DH 128
#define Fdim 4096
#define NTOK (Bn*S)
#define Ldim 6

// ---------------- fp32 scratch ----------------
__device__ float g_x [(size_t)NTOK*D];             // residual stream

// ---------------- fp16 buffers ----------------
__device__ __align__(256) half g_h1[(size_t)Bn*T1*D];   // conv1 out [b][t][d]
__device__ __align__(256) half c1w[(size_t)D*384];
__device__ __align__(256) half c2w[(size_t)D*3072];     // reordered: [d][kk*1024+i]
__device__ __align__(256) half wq[(size_t)Ldim*D*D];
__device__ __align__(256) half wk[(size_t)Ldim*D*D];
__device__ __align__(256) half wv[(size_t)Ldim*D*D];
__device__ __align__(256) half wo[(size_t)Ldim*D*D];
__device__ __align__(256) half w1[(size_t)Ldim*Fdim*D];
__device__ __align__(256) half w2[(size_t)Ldim*Fdim*D];
__device__ __align__(256) half g_col[(size_t)Bn*T1*384];
__device__ __align__(256) half g_y [(size_t)NTOK*D];
__device__ __align__(256) half g_q [(size_t)NTOK*D];
__device__ __align__(256) half g_k [(size_t)NTOK*D];
__device__ __align__(256) half g_vt[(size_t)D*NTOK];
__device__ __align__(256) half g_m1[(size_t)NTOK*Fdim];
__device__ __align__(256) half g_o [(size_t)NTOK*D];

// ---------------- helpers ----------------
__device__ __forceinline__ float gelu_exact(float v) {
    return 0.5f * v * (1.0f + erff(v * 0.70710678118654752f));
}
__device__ __forceinline__ void mma_fp16(float* d, const u32* a, const u32* b) {
    asm volatile(
        "mma.sync.aligned.m16n8k16.row.col.f32.f16.f16.f32 "
        "{%0,%1,%2,%3}, {%4,%5,%6,%7}, {%8,%9}, {%0,%1,%2,%3};\n"
        : "+f"(d[0]), "+f"(d[1]), "+f"(d[2]), "+f"(d[3])
        : "r"(a[0]), "r"(a[1]), "r"(a[2]), "r"(a[3]), "r"(b[0]), "r"(b[1]));
}
__device__ __forceinline__ void ldsm4(u32* r, u32 addr) {
    asm volatile("ldmatrix.sync.aligned.m8n8.x4.shared.b16 {%0,%1,%2,%3}, [%4];\n"
        : "=r"(r[0]), "=r"(r[1]), "=r"(r[2]), "=r"(r[3]) : "r"(addr));
}
__device__ __forceinline__ void cpa16(u32 dst, const void* src) {
    asm volatile("cp.async.cg.shared.global [%0], [%1], 16;\n" :: "r"(dst), "l"(src));
}
__device__ __forceinline__ void cpa16p(u32 dst, const void* src, int pred) {
    int sz = pred ? 16 : 0;
    asm volatile("cp.async.cg.shared.global [%0], [%1], 16, %2;\n" :: "r"(dst), "l"(src), "r"(sz));
}
__device__ __forceinline__ u32 packh2(float lo, float hi) {
    __half2 h = __floats2half2_rn(lo, hi);
    return *(u32*)&h;
}

// ---------------- fp16 tensor-core GEMM (16 warps, 128x128 tile, KC=64, 3-stage) ----------------
// C[M,N] = A[M,K] * B[N,K]^T
#define KC 64
#define NSTG 3
#define PADR 72
#define TILE_E (128*PADR)
#define TILE_B2 (TILE_E*2)
#define STG_B  (2*TILE_B2)
#define SMEM_TOT (NSTG*STG_B)        // 110592

struct GemmP {
    const half *A, *B;
    const half *Bk, *Bv;     // qkvZ weight pointers for z=1,2
    float* C; half *Cs;
    half *Qd, *Kd, *Vd;      // qkvZ outputs
    const float* Cin;
    const float* bias;
    const float* bias2;      // qkvZ: v bias
    int K, lda, ldb, ldc;
    int zDiv;
    ll sAo, sAi, sBo, sBi, sCo, sCi;
    int biasMode;   // 0 none, 1 per-col(n), 2 per-row(m)
    int addC;
    int act;        // 0 none, 1 exact GELU, 2 RoPE+scale
    int transStore;
    int outF32, outHalf;
    int aConv;
    int qkvZ;       // grid.z selects q/k/v
};

__device__ __forceinline__ void rope2(float& v0, float& v1, int m, int cB) {
    int s = m & (S - 1);
    int j = (cB & 127) >> 1;
    float freq = powf(10000.f, -(float)(2 * j) * (1.f / 128.f));
    float ang = (float)s * freq;
    float cc, ss; sincosf(ang, &ss, &cc);
    const float sc = 0.29730177875068026f;  // 128^-0.25
    float r0 = (v0 * cc - v1 * ss) * sc;
    float r1 = (v0 * ss + v1 * cc) * sc;
    v0 = r0; v1 = r1;
}

__global__ __launch_bounds__(512, 1) void gemm_tc(GemmP p) {
    extern __shared__ __align__(16) half sm[];
    int z = blockIdx.z;
    ll offA = 0, offB = 0, offC = 0;
    const half* A = p.A;
    const half* B = p.B;
    if (p.qkvZ) {
        B = (z == 0) ? p.B : (z == 1) ? p.Bk : p.Bv;
    } else {
        offA = (ll)(z / p.zDiv) * p.sAo + (ll)(z % p.zDiv) * p.sAi;
        offB = (ll)(z / p.zDiv) * p.sBo + (ll)(z % p.zDiv) * p.sBi;
        offC = (ll)(z / p.zDiv) * p.sCo + (ll)(z % p.zDiv) * p.sCi;
        A += offA; B += offB;
    }

    int m0 = blockIdx.y * 128, n0 = blockIdx.x * 128;
    int tid = threadIdx.x, lane = tid & 31, wid = tid >> 5;
    int wm = (wid & 3) * 32, wn = (wid >> 2) * 32;
    u32 smu = (u32)__cvta_generic_to_shared(sm);

    float acc[2][4][4];
    #pragma unroll
    for (int a = 0; a < 2; a++)
        #pragma unroll
        for (int b = 0; b < 4; b++)
            #pragma unroll
            for (int c = 0; c < 4; c++) acc[a][b][c] = 0.f;

    int ldRow = tid >> 3;
    int ldCC  = (tid & 7) * 8;

    auto issue = [&](int c) {
        u32 base = smu + (u32)(c % NSTG) * STG_B;
        int k0 = c * KC;
        #pragma unroll
        for (int hh = 0; hh < 2; hh++) {
            int row = ldRow + hh * 64;
            u32 so = (u32)(row * PADR + ldCC) * 2;
            if (p.aConv) {
                int kk = k0 >> 10;
                int i0 = (k0 & 1023) + ldCC;
                int pos = 2 * (m0 + row) + kk - 1;
                const half* src = A + (ll)(pos < 0 ? 0 : pos) * 1024 + i0;
                cpa16p(base + so, src, pos >= 0);
            } else {
                cpa16(base + so, A + (ll)(m0 + row) * p.lda + k0 + ldCC);
            }
            cpa16(base + TILE_B2 + so, B + (ll)(n0 + row) * p.ldb + k0 + ldCC);
        }
        asm volatile("cp.async.commit_group;" ::: "memory");
    };

    int nch = p.K / KC;
    issue(0);
    if (nch > 1) issue(1);

    for (int c = 0; c < nch; c++) {
        if (c + 1 < nch) asm volatile("cp.async.wait_group 1;" ::: "memory");
        else             asm volatile("cp.async.wait_group 0;" ::: "memory");
        __syncthreads();
        if (c + 2 < nch) issue(c + 2);

        u32 aB = smu + (u32)(c % NSTG) * STG_B;
        u32 bB = aB + TILE_B2;

        #pragma unroll
        for (int ks = 0; ks < 4; ks++) {
            u32 ar[2][4], br[4][2];
            #pragma unroll
            for (int mi = 0; mi < 2; mi++) {
                int row = wm + mi * 16 + (lane & 15);
                int col = ks * 16 + (lane >> 4) * 8;
                ldsm4(ar[mi], aB + (u32)(row * PADR + col) * 2);
            }
            #pragma unroll
            for (int nj = 0; nj < 2; nj++) {
                int g = lane >> 3;
                int row = wn + nj * 16 + ((g >> 1) << 3) + (lane & 7);
                int col = ks * 16 + ((g & 1) << 3);
                u32 t[4];
                ldsm4(t, bB + (u32)(row * PADR + col) * 2);
                br[nj*2][0] = t[0]; br[nj*2][1] = t[1];
                br[nj*2+1][0] = t[2]; br[nj*2+1][1] = t[3];
            }
            #pragma unroll
            for (int mi = 0; mi < 2; mi++)
                #pragma unroll
                for (int nf = 0; nf < 4; nf++)
                    mma_fp16(acc[mi][nf], ar[mi], br[nf]);
        }
    }

    float* Cp = p.C  ? p.C  + offC : nullptr;
    half* Csp = p.Cs ? p.Cs + offC : nullptr;
    const float* Rp = p.Cin ? p.Cin + offC : Cp;
    #pragma unroll
    for (int mi = 0; mi < 2; mi++)
        #pragma unroll
        for (int nf = 0; nf < 4; nf++) {
            int rB = m0 + wm + mi * 16 + (lane >> 2);
            int cB = n0 + wn + nf * 8 + (lane & 3) * 2;
            #pragma unroll
            for (int pe = 0; pe < 2; pe++) {
                int m = rB + pe * 8;
                float v0 = acc[mi][nf][pe * 2 + 0];
                float v1 = acc[mi][nf][pe * 2 + 1];

                if (p.qkvZ) {
                    int z2 = blockIdx.z;
                    if (z2 == 0) {
                        v0 += p.bias[cB]; v1 += p.bias[cB + 1];
                        rope2(v0, v1, m, cB);
                        *(u32*)&p.Qd[(ll)m * D + cB] = packh2(v0, v1);
                    } else if (z2 == 1) {
                        rope2(v0, v1, m, cB);
                        *(u32*)&p.Kd[(ll)m * D + cB] = packh2(v0, v1);
                    } else {
                        v0 += p.bias2[cB]; v1 += p.bias2[cB + 1];
                        p.Vd[(ll)cB * NTOK + m]       = __float2half_rn(v0);
                        p.Vd[(ll)(cB + 1) * NTOK + m] = __float2half_rn(v1);
                    }
                    continue;
                }

                if (p.biasMode == 1) { v0 += p.bias[cB]; v1 += p.bias[cB + 1]; }
                else if (p.biasMode == 2) { float bb = p.bias[m]; v0 += bb; v1 += bb; }
                if (p.act == 1) { v0 = gelu_exact(v0); v1 = gelu_exact(v1); }
                else if (p.act == 2) rope2(v0, v1, m, cB);

                if (!p.transStore) {
                    ll off0 = (ll)m * p.ldc + cB;
                    if (p.outF32) {
                        float w0 = v0, w1 = v1;
                        if (p.addC) {
                            float2 o = *(const float2*)&Rp[off0];
                            w0 += o.x; w1 += o.y;
                        }
                        *(float2*)&Cp[off0] = make_float2(w0, w1);
                    }
                    if (p.outHalf) *(u32*)&Csp[off0] = packh2(v0, v1);
                } else {
                    ll off0 = (ll)cB * p.ldc + m;
                    ll off1 = off0 + p.ldc;
                    if (p.outF32) {
                        float w0 = v0, w1 = v1;
                        if (p.addC) { w0 += Rp[off0]; w1 += Rp[off1]; }
                        Cp[off0] = w0; Cp[off1] = w1;
                    }
                    if (p.outHalf) {
                        Csp[off0] = __float2half_rn(v0);
                        Csp[off1] = __float2half_rn(v1);
                    }
                }
            }
        }
}

// ---------------- fused flash attention (K-prefetch pipelined) ----------------
#define FP2 136
#define FSM_BYTES ((128+128+128)*FP2*2)    // 104448

__global__ __launch_bounds__(256) void attn_k(const int* __restrict__ x_len) {
    extern __shared__ __align__(16) half fsm[];
    int tid = threadIdx.x, lane = tid & 31, wid = tid >> 5;
    int bh = blockIdx.y, b = bh >> 3, h = bh & 7;
    int m0 = blockIdx.x * 128;
    int wm = wid * 16;
    u32 smu = (u32)__cvta_generic_to_shared(fsm);
    u32 sQ = smu;
    u32 sK = smu + (u32)(128 * FP2) * 2;
    u32 sV = sK + (u32)(128 * FP2) * 2;

    const half* qp = g_q + ((ll)(b * S + m0)) * D + h * 128;
    const half* kp = g_k + ((ll)b * S) * D + h * 128;
    const half* vp = g_vt + ((ll)(h * 128)) * NTOK + (ll)b * S;

    // Q group
    #pragma unroll
    for (int i = 0; i < 8; i++) {
        int idx = tid + 256 * i, row = idx >> 4, ch = idx & 15;
        cpa16(sQ + (u32)(row * FP2 + ch * 8) * 2, qp + (ll)row * D + ch * 8);
    }
    asm volatile("cp.async.commit_group;" ::: "memory");
    // K(0) prefetch group
    #pragma unroll
    for (int i = 0; i < 8; i++) {
        int idx = tid + 256 * i, row = idx >> 4, ch = idx & 15;
        cpa16(sK + (u32)(row * FP2 + ch * 8) * 2, kp + (ll)row * D + ch * 8);
    }
    asm volatile("cp.async.commit_group;" ::: "memory");

    int xl = x_len[b];
    int quad = lane >> 2, qi = lane & 3;
    float mrow[2] = {-1e30f, -1e30f}, lrow[2] = {0.f, 0.f};
    float oacc[16][4];
    #pragma unroll
    for (int nt = 0; nt < 16; nt++)
        #pragma unroll
        for (int e = 0; e < 4; e++) oacc[nt][e] = 0.f;

    for (int kv0 = 0; kv0 < S; kv0 += 128) {
        if (kv0) __syncthreads();   // sV reads from previous PV done
        // V(i) group
        #pragma unroll
        for (int i = 0; i < 8; i++) {
            int idx = tid + 256 * i, row = idx >> 4, ch = idx & 15;
            cpa16(sV + (u32)(row * FP2 + ch * 8) * 2, vp + (ll)row * NTOK + kv0 + ch * 8);
        }
        asm volatile("cp.async.commit_group;" ::: "memory");
        // wait K(i) (V(i) stays in flight)
        asm volatile("cp.async.wait_group 1;" ::: "memory");
        __syncthreads();

        // S = Q @ K^T
        float sacc[16][4];
        #pragma unroll
        for (int nt = 0; nt < 16; nt++)
            #pragma unroll
            for (int e = 0; e < 4; e++) sacc[nt][e] = 0.f;

        #pragma unroll
        for (int ks = 0; ks < 8; ks++) {
            u32 aq[4];
            ldsm4(aq, sQ + (u32)((wm + (lane & 15)) * FP2 + ks * 16 + (lane >> 4) * 8) * 2);
            #pragma unroll
            for (int njp = 0; njp < 8; njp++) {
                int g = lane >> 3;
                int row = njp * 16 + ((g >> 1) << 3) + (lane & 7);
                int col = ks * 16 + ((g & 1) << 3);
                u32 t[4];
                ldsm4(t, sK + (u32)(row * FP2 + col) * 2);
                u32 b0[2] = {t[0], t[1]}, b1[2] = {t[2], t[3]};
                mma_fp16(sacc[njp*2],   aq, b0);
                mma_fp16(sacc[njp*2+1], aq, b1);
            }
        }
        __syncthreads();            // all warps done reading sK
        int hasNext = (kv0 + 128 < S);
        if (hasNext) {              // K(i+1) prefetch into freed sK
            #pragma unroll
            for (int i = 0; i < 8; i++) {
                int idx = tid + 256 * i, row = idx >> 4, ch = idx & 15;
                cpa16(sK + (u32)(row * FP2 + ch * 8) * 2, kp + (ll)(kv0 + 128 + row) * D + ch * 8);
            }
            asm volatile("cp.async.commit_group;" ::: "memory");
        }

        // mask + online softmax (overlaps V(i) completion and K(i+1) flight)
        float rmax[2] = {-1e30f, -1e30f};
        #pragma unroll
        for (int nt = 0; nt < 16; nt++)
            #pragma unroll
            for (int e = 0; e < 4; e++) {
                int col = kv0 + nt * 8 + qi * 2 + (e & 1);
                float v = sacc[nt][e] + ((4 * col + 3 < xl) ? 0.f : -1e10f);
                sacc[nt][e] = v;
                rmax[e >> 1] = fmaxf(rmax[e >> 1], v);
            }
        #pragma unroll
        for (int s2 = 1; s2 < 4; s2 <<= 1) {
            rmax[0] = fmaxf(rmax[0], __shfl_xor_sync(0xffffffff, rmax[0], s2));
            rmax[1] = fmaxf(rmax[1], __shfl_xor_sync(0xffffffff, rmax[1], s2));
        }
        float mn0 = fmaxf(mrow[0], rmax[0]), mn1 = fmaxf(mrow[1], rmax[1]);
        float sc0 = expf(mrow[0] - mn0), sc1 = expf(mrow[1] - mn1);
        float rsum[2] = {0.f, 0.f};
        #pragma unroll
        for (int nt = 0; nt < 16; nt++)
            #pragma unroll
            for (int e = 0; e < 4; e++) {
                float v = expf(sacc[nt][e] - ((e >> 1) ? mn1 : mn0));
                sacc[nt][e] = v;
                rsum[e >> 1] += v;
            }
        #pragma unroll
        for (int s2 = 1; s2 < 4; s2 <<= 1) {
            rsum[0] += __shfl_xor_sync(0xffffffff, rsum[0], s2);
            rsum[1] += __shfl_xor_sync(0xffffffff, rsum[1], s2);
        }
        lrow[0] = lrow[0] * sc0 + rsum[0];
        lrow[1] = lrow[1] * sc1 + rsum[1];
        mrow[0] = mn0; mrow[1] = mn1;
        #pragma unroll
        for (int nt = 0; nt < 16; nt++) {
            oacc[nt][0] *= sc0; oacc[nt][1] *= sc0;
            oacc[nt][2] *= sc1; oacc[nt][3] *= sc1;
        }

        // wait V(i): if K(i+1) issued it may stay in flight (groups retire in order)
        if (hasNext) asm volatile("cp.async.wait_group 1;" ::: "memory");
        else         asm volatile("cp.async.wait_group 0;" ::: "memory");
        __syncthreads();

        // O += P @ V
        #pragma unroll
        for (int j = 0; j < 8; j++) {
            u32 af[4];
            af[0] = packh2(sacc[2*j][0],   sacc[2*j][1]);
            af[1] = packh2(sacc[2*j][2],   sacc[2*j][3]);
            af[2] = packh2(sacc[2*j+1][0], sacc[2*j+1][1]);
            af[3] = packh2(sacc[2*j+1][2], sacc[2*j+1][3]);
            #pragma unroll
            for (int njp = 0; njp < 8; njp++) {
                int g = lane >> 3;
                int row = njp * 16 + ((g >> 1) << 3) + (lane & 7);
                int col = j * 16 + ((g & 1) << 3);
                u32 t[4];
                ldsm4(t, sV + (u32)(row * FP2 + col) * 2);
                u32 b0[2] = {t[0], t[1]}, b1[2] = {t[2], t[3]};
                mma_fp16(oacc[njp*2],   af, b0);
                mma_fp16(oacc[njp*2+1], af, b1);
            }
        }
    }

    float inv0 = 1.f / lrow[0], inv1 = 1.f / lrow[1];
    half* op = g_o + ((ll)(b * S + m0 + wm)) * D + h * 128;
    #pragma unroll
    for (int nt = 0; nt < 16; nt++)
        #pragma unroll
        for (int pe = 0; pe < 2; pe++) {
            int row = quad + pe * 8;
            float iv = pe ? inv1 : inv0;
            u32 pk = packh2(oacc[nt][pe*2] * iv, oacc[nt][pe*2+1] * iv);
            *(u32*)&op[(ll)row * D + nt * 8 + qi * 2] = pk;
        }
}

// ---------------- weight converts (16 elems/thread, packed 16B stores) ----------------
__global__ void cvt_k(const float* __restrict__ in, half* __restrict__ out, ll n) {
    ll i = ((ll)blockIdx.x * 256 + threadIdx.x) * 16;
    if (i >= n) return;
    float4 a = *(const float4*)&in[i];
    float4 b = *(const float4*)&in[i + 4];
    float4 c = *(const float4*)&in[i + 8];
    float4 d = *(const float4*)&in[i + 12];
    uint4 o1, o2;
    o1.x = packh2(a.x, a.y); o1.y = packh2(a.z, a.w);
    o1.z = packh2(b.x, b.y); o1.w = packh2(b.z, b.w);
    o2.x = packh2(c.x, c.y); o2.y = packh2(c.z, c.w);
    o2.z = packh2(d.x, d.y); o2.w = packh2(d.z, d.w);
    *(uint4*)&out[i] = o1;
    *(uint4*)&out[i + 8] = o2;
}
// conv2 weights: out[d][kk*1024+i] = in[d][i*3+kk]
__global__ void cvt_c2_k(const float* __restrict__ in, half* __restrict__ out) {
    ll idx = (ll)blockIdx.x * 256 + threadIdx.x;
    if (idx >= (ll)D * 3072) return;
    int rp = (int)(idx % 3072);
    int d  = (int)(idx / 3072);
    int kk = rp >> 10, i = rp & 1023;
    out[idx] = __float2half_rn(in[(ll)d * 3072 + i * 3 + kk]);
}

// ---------------- im2col for conv1 ----------------
__global__ void im2col1_k(const float* __restrict__ x) {
    int idx = blockIdx.x * 256 + threadIdx.x;
    const int total = Bn * T1 * 384;
    if (idx >= total) return;
    int r = idx % 384;
    int t = (idx / 384) % T1;
    int b = idx / (384 * T1);
    int i = r / 3, kk = r % 3;
    int pos = 2 * t + kk - 1;
    float v = (pos >= 0 && pos < TIN) ? x[((ll)b * NMELS + i) * TIN + pos] : 0.f;
    g_col[idx] = __float2half_rn(v);
}

// ---------------- LayerNorm -> fp16 (shuffle reductions, vectorized I/O) ----------------
__global__ void ln_k(const float* __restrict__ x,
                     const float* __restrict__ w, const float* __restrict__ b) {
    int row = blockIdx.x;
    int tid = threadIdx.x, lane = tid & 31, wid = tid >> 5;
    const float* xr = x + (ll)row * D;
    __shared__ float red[8];
    __shared__ float bc;
    float4 v4 = *(const float4*)&xr[tid * 4];
    float v[4] = {v4.x, v4.y, v4.z, v4.w};

    float s = v[0] + v[1] + v[2] + v[3];
    #pragma unroll
    for (int o = 16; o > 0; o >>= 1) s += __shfl_xor_sync(0xffffffff, s, o);
    if (lane == 0) red[wid] = s;
    __syncthreads();
    if (tid < 8) {
        float t = red[tid];
        #pragma unroll
        for (int o = 4; o > 0; o >>= 1) t += __shfl_xor_sync(0xff, t, o);
        if (tid == 0) bc = t;
    }
    __syncthreads();
    float mean = bc * (1.f / D);

    float sq = 0.f;
    #pragma unroll
    for (int i = 0; i < 4; i++) { float d0 = v[i] - mean; sq += d0 * d0; }
    #pragma unroll
    for (int o = 16; o > 0; o >>= 1) sq += __shfl_xor_sync(0xffffffff, sq, o);
    if (lane == 0) red[wid] = sq;
    __syncthreads();
    if (tid < 8) {
        float t = red[tid];
        #pragma unroll
        for (int o = 4; o > 0; o >>= 1) t += __shfl_xor_sync(0xff, t, o);
        if (tid == 0) bc = t;
    }
    __syncthreads();
    float rstd = rsqrtf(bc * (1.f / D) + 1e-5f);

    int c = tid * 4;
    float4 w4 = *(const float4*)&w[c];
    float4 b4 = *(const float4*)&b[c];
    float y0 = (v[0] - mean) * rstd * w4.x + b4.x;
    float y1 = (v[1] - mean) * rstd * w4.y + b4.y;
    float y2 = (v[2] - mean) * rstd * w4.z + b4.z;
    float y3 = (v[3] - mean) * rstd * w4.w + b4.w;
    uint2 pk = make_uint2(packh2(y0, y1), packh2(y2, y3));
    *(uint2*)&g_y[(ll)row * D + c] = pk;
}

// ---------------- y_len tail ----------------
__global__ void ylen_k(float* __restrict__ out, const int* __restrict__ x_len, ll out_size) {
    int i = threadIdx.x;
    if (i < Bn) {
        ll pos = (ll)NTOK * D + i;
        if (pos < out_size) {
            int yl = (x_len[i] + 1) / 2;
            yl = (yl + 1) / 2;
            out[pos] = (float)yl;
        }
    }
}

// ---------------- host launcher ----------------
extern "C" void kernel_launch(void* const* d_in, const int* in_sizes, int n_in,
                              void* d_out, int out_size) {
    const float* x        = (const float*)d_in[0];
    const int*   x_len    = (const int*)  d_in[1];
    const float* conv1_w  = (const float*)d_in[2];
    const float* conv1_b  = (const float*)d_in[3];
    const float* conv2_w  = (const float*)d_in[4];
    const float* conv2_b  = (const float*)d_in[5];
    const float* attn_ln_w= (const float*)d_in[6];
    const float* attn_ln_b= (const float*)d_in[7];
    const float* q_w      = (const float*)d_in[8];
    const float* q_b      = (const float*)d_in[9];
    const float* k_w      = (const float*)d_in[10];
    const float* v_w      = (const float*)d_in[11];
    const float* v_b      = (const float*)d_in[12];
    const float* out_w    = (const float*)d_in[13];
    const float* out_b    = (const float*)d_in[14];
    const float* mlp_ln_w = (const float*)d_in[15];
    const float* mlp_ln_b = (const float*)d_in[16];
    const float* mlp1_w   = (const float*)d_in[17];
    const float* mlp1_b   = (const float*)d_in[18];
    const float* mlp2_w   = (const float*)d_in[19];
    const float* mlp2_b   = (const float*)d_in[20];

    cudaFuncSetAttribute(gemm_tc, cudaFuncAttributeMaxDynamicSharedMemorySize, SMEM_TOT);
    cudaFuncSetAttribute(attn_k,  cudaFuncAttributeMaxDynamicSharedMemorySize, FSM_BYTES);

    // side stream for weight conversions (created once, outside capture)
    static cudaStream_t s1 = 0;
    static cudaEvent_t ev0 = 0, ev1 = 0;
    if (!s1) {
        cudaStreamCreateWithFlags(&s1, cudaStreamNonBlocking);
        cudaEventCreateWithFlags(&ev0, cudaEventDisableTiming);
        cudaEventCreateWithFlags(&ev1, cudaEventDisableTiming);
    }

    #define SYM(p, s) do { void* _t; cudaGetSymbolAddress(&_t, s); p = (decltype(p))_t; } while (0)
    float *xs;
    SYM(xs, g_x);
    half *ph1, *pc1, *pc2, *pwq, *pwk, *pwv, *pwo, *pw1, *pw2;
    half *pcol, *py, *pq, *pk, *pvt, *pm1, *po;
    SYM(ph1, g_h1);
    SYM(pc1, c1w); SYM(pc2, c2w);
    SYM(pwq, wq); SYM(pwk, wk); SYM(pwv, wv); SYM(pwo, wo);
    SYM(pw1, w1); SYM(pw2, w2);
    SYM(pcol, g_col); SYM(py, g_y); SYM(pq, g_q); SYM(pk, g_k);
    SYM(pvt, g_vt); SYM(pm1, g_m1); SYM(po, g_o);

    auto cvtOn = [&](cudaStream_t st, const float* in, half* out, ll n) {
        cvt_k<<<(int)((n / 16 + 255) / 256), 256, 0, st>>>(in, out, n);
    };

    // fork: transformer weight cvts on s1, overlapping the conv phase
    cudaEventRecord(ev0, 0);
    cudaStreamWaitEvent(s1, ev0, 0);
    cvtOn(s1, q_w,   pwq, (ll)Ldim * D * D);
    cvtOn(s1, k_w,   pwk, (ll)Ldim * D * D);
    cvtOn(s1, v_w,   pwv, (ll)Ldim * D * D);
    cvtOn(s1, out_w, pwo, (ll)Ldim * D * D);
    cvtOn(s1, mlp1_w, pw1, (ll)Ldim * Fdim * D);
    cvtOn(s1, mlp2_w, pw2, (ll)Ldim * Fdim * D);
    cudaEventRecord(ev1, s1);

    // conv-phase cvts on default stream
    cvtOn(0, conv1_w, pc1, (ll)D * 384);
    cvt_c2_k<<<(int)(((ll)D * 3072 + 255) / 256), 256>>>(conv2_w, pc2);

    auto gemm = [&](const half* A, const half* B,
                    float* C, half* Cs, const float* bias,
                    int M, int N, int K, int lda, int ldb, int ldc,
                    int nz, int zDiv,
                    ll sAo, ll sAi, ll sBo, ll sBi, ll sCo, ll sCi,
                    int biasMode, int addC, int act, int transStore,
                    int outF32, int outHalf, const float* Cin = 0, int aConv = 0) {
        GemmP p = {};
        p.A = A; p.B = B;
        p.C = C; p.Cs = Cs; p.Cin = Cin; p.bias = bias;
        p.K = K; p.lda = lda; p.ldb = ldb; p.ldc = ldc;
        p.zDiv = zDiv;
        p.sAo = sAo; p.sAi = sAi; p.sBo = sBo; p.sBi = sBi; p.sCo = sCo; p.sCi = sCi;
        p.biasMode = biasMode; p.addC = addC; p.act = act;
        p.transStore = transStore;
        p.outF32 = outF32; p.outHalf = outHalf; p.aConv = aConv;
        p.qkvZ = 0;
        dim3 g(N / 128, M / 128, nz);
        gemm_tc<<<g, 512, SMEM_TOT>>>(p);
    };

    const ll SD = (ll)S * D;

    // conv1: im2col + GEMM -> g_h1 fp16
    im2col1_k<<<(Bn * T1 * 384 + 255) / 256, 256>>>(x);
    gemm(pcol, pc1, 0, ph1, conv1_b,
         T1, 1024, 384, 384, 384, D,
         Bn, 1, (ll)T1 * 384, 0, 0, 0, (ll)T1 * D, 0,
         1, 0, 1, 0, 0, 1);

    // conv2: direct read from g_h1 (kk-major K, zero-fill boundary) -> g_x fp32
    gemm(ph1, pc2, xs, 0, conv2_b,
         S, 1024, 3072, 1024, 3072, D,
         Bn, 1, (ll)T1 * D, 0, 0, 0, SD, 0,
         1, 0, 1, 0, 1, 0, 0, 1);

    // join: transformer weights ready
    cudaStreamWaitEvent(0, ev1, 0);

    for (int l = 0; l < 6; l++) {
        const float* aw = attn_ln_w + l * D;  const float* ab = attn_ln_b + l * D;
        const float* qb = q_b + l * D;
        const float* vb = v_b + l * D;
        const float* ob = out_b + l * D;
        const float* mw = mlp_ln_w + l * D;   const float* mb2 = mlp_ln_b + l * D;
        const float* b1 = mlp1_b + l * Fdim;
        const float* b2 = mlp2_b + l * D;
        ll wOff = (ll)l * D * D;
        ll mOff = (ll)l * Fdim * D;

        ln_k<<<NTOK, 256>>>(xs, aw, ab);

        // fused qkv: one launch, grid.z selects q/k/v (uniform per-CTA epilogue)
        {
            GemmP p = {};
            p.A = py;
            p.B = pwq + wOff; p.Bk = pwk + wOff; p.Bv = pwv + wOff;
            p.Qd = pq; p.Kd = pk; p.Vd = pvt;
            p.bias = qb; p.bias2 = vb;
            p.K = D; p.lda = D; p.ldb = D; p.ldc = D;
            p.zDiv = 1;
            p.qkvZ = 1;
            dim3 g(D / 128, NTOK / 128, 3);
            gemm_tc<<<g, 512, SMEM_TOT>>>(p);
        }

        // fused flash attention -> g_o fp16
        attn_k<<<dim3(S / 128, Bn * H), 256, FSM_BYTES>>>(x_len);

        // out projection + residual
        gemm(po, pwo + wOff, xs, 0, ob,
             NTOK, D, D, D, D, D, 1, 1, 0,0,0,0,0,0, 1, 1, 0, 0, 1, 0);

        // MLP (last layer's mlp2 writes directly to d_out)
        ln_k<<<NTOK, 256>>>(xs, mw, mb2);
        gemm(py, pw1 + mOff, 0, pm1, b1,
             NTOK, Fdim, D, D, D, Fdim, 1, 1, 0,0,0,0,0,0, 1, 0, 1, 0, 0, 1);
        if (l < 5) {
            gemm(pm1, pw2 + mOff, xs, 0, b2,
                 NTOK, D, Fdim, Fdim, Fdim, D, 1, 1, 0,0,0,0,0,0, 1, 1, 0, 0, 1, 0);
        } else {
            gemm(pm1, pw2 + mOff, (float*)d_out, 0, b2,
                 NTOK, D, Fdim, Fdim, Fdim, D, 1, 1, 0,0,0,0,0,0, 1, 1, 0, 0, 1, 0, xs);
        }
    }

    ylen_k<<<1, 32>>>((float*)d_out, x_len, (ll)out_size);
}